// round 2
// baseline (speedup 1.0000x reference)
#include <cuda_runtime.h>

// Problem constants
#define BATCH 8
#define SEQ   1024
#define CH    256
#define PDIM  16
#define EPSV  1e-5f

// Scratch for per-batch output vector o[b][c] (no cudaMalloc allowed)
__device__ float g_o[BATCH * CH];

// ---------------------------------------------------------------------------
// Kernel A: per-batch chain  ctx -> LN -> v = y@Wkv[:,C:] -> o = v@Wout + bout
// 8 blocks (one per batch), 256 threads (one per channel).
// ---------------------------------------------------------------------------
__global__ void __launch_bounds__(CH) compute_o_kernel(
    const float* __restrict__ param,    // (B, 16)
    const float* __restrict__ Wparam,   // (16, 256)
    const float* __restrict__ bparam,   // (256)
    const float* __restrict__ gamma,    // ctx_norm_g (256)
    const float* __restrict__ beta,     // ctx_norm_b (256)
    const float* __restrict__ Wkv,      // (256, 512)
    const float* __restrict__ Wout,     // (256, 256)
    const float* __restrict__ bout)     // (256)
{
    const int b = blockIdx.x;
    const int c = threadIdx.x;

    __shared__ float sh_y[CH];
    __shared__ float sh_v[CH];
    __shared__ float red[8];

    // ctx[b][c] = param[b,:] @ Wparam[:,c] + bparam[c]
    float ctx = bparam[c];
    #pragma unroll
    for (int p = 0; p < PDIM; p++)
        ctx = fmaf(param[b * PDIM + p], Wparam[p * CH + c], ctx);

    // ---- mean over the 256 channels ----
    float s = ctx;
    #pragma unroll
    for (int off = 16; off > 0; off >>= 1)
        s += __shfl_xor_sync(0xffffffffu, s, off);
    if ((c & 31) == 0) red[c >> 5] = s;
    __syncthreads();
    float mean = 0.f;
    #pragma unroll
    for (int i = 0; i < 8; i++) mean += red[i];
    mean *= (1.0f / CH);

    // ---- variance ----
    float d = ctx - mean;
    float s2 = d * d;
    __syncthreads();   // protect red before reuse
    #pragma unroll
    for (int off = 16; off > 0; off >>= 1)
        s2 += __shfl_xor_sync(0xffffffffu, s2, off);
    if ((c & 31) == 0) red[c >> 5] = s2;
    __syncthreads();
    float var = 0.f;
    #pragma unroll
    for (int i = 0; i < 8; i++) var += red[i];
    var *= (1.0f / CH);

    // ---- layernorm ----
    float y = d * rsqrtf(var + EPSV) * gamma[c] + beta[c];
    sh_y[c] = y;
    __syncthreads();

    // ---- v[c] = sum_j y[j] * Wkv[j, 256 + c] ----
    float accv = 0.f;
    #pragma unroll 4
    for (int j = 0; j < CH; j++)
        accv = fmaf(sh_y[j], Wkv[j * (2 * CH) + CH + c], accv);
    sh_v[c] = accv;
    __syncthreads();

    // ---- o[c] = sum_j v[j] * Wout[j, c] + bout[c] ----
    float acco = bout[c];
    #pragma unroll 4
    for (int j = 0; j < CH; j++)
        acco = fmaf(sh_v[j], Wout[j * CH + c], acco);

    g_o[b * CH + c] = acco;
}

// ---------------------------------------------------------------------------
// Kernel B: out[b,n,c] = img[b,n,c] + o[b,c]   (HBM-bound broadcast add)
// One float4 per thread: 8*1024*256 floats = 524288 float4 = 2048 blocks x 256
// ---------------------------------------------------------------------------
__global__ void __launch_bounds__(256) broadcast_add_kernel(
    const float* __restrict__ img,
    float* __restrict__ out)
{
    const int i = blockIdx.x * blockDim.x + threadIdx.x;   // float4 index
    const int base = i << 2;                               // element index
    const int c = base & (CH - 1);                         // channel
    const int b = base >> 18;                              // 1024*256 = 2^18

    float4 x = reinterpret_cast<const float4*>(img)[i];
    float4 ov = *reinterpret_cast<const float4*>(&g_o[b * CH + c]);
    x.x += ov.x; x.y += ov.y; x.z += ov.z; x.w += ov.w;
    reinterpret_cast<float4*>(out)[i] = x;
}

// ---------------------------------------------------------------------------
// Launch. Input order (metadata): img_tokens, param_tokens, img_norm_g,
// img_norm_b, Wq, Wparam, bparam, ctx_norm_g, ctx_norm_b, Wkv, Wout, bout
// ---------------------------------------------------------------------------
extern "C" void kernel_launch(void* const* d_in, const int* in_sizes, int n_in,
                              void* d_out, int out_size)
{
    const float* img    = (const float*)d_in[0];
    const float* param  = (const float*)d_in[1];
    // d_in[2], d_in[3]: img LN params (dead code — q is never used)
    // d_in[4]: Wq (dead code)
    const float* Wparam = (const float*)d_in[5];
    const float* bparam = (const float*)d_in[6];
    const float* ctx_g  = (const float*)d_in[7];
    const float* ctx_b  = (const float*)d_in[8];
    const float* Wkv    = (const float*)d_in[9];
    const float* Wout   = (const float*)d_in[10];
    const float* bout   = (const float*)d_in[11];
    float* out = (float*)d_out;

    compute_o_kernel<<<BATCH, CH>>>(param, Wparam, bparam, ctx_g, ctx_b,
                                    Wkv, Wout, bout);

    const int total4 = (BATCH * SEQ * CH) / 4;   // 524288
    broadcast_add_kernel<<<total4 / 256, 256>>>(img, out);
}

// round 3
// speedup vs baseline: 3.3892x; 3.3892x over previous
#include <cuda_runtime.h>

#define BATCH 8
#define SEQ   1024
#define CH    256
#define PDIM  16
#define EPSV  1e-5f
#define NS    8          // j-splits per GEMV stage
#define JSP   (CH / NS)  // 32 rows per split

// Scratch (no cudaMalloc allowed)
__device__ float g_vp[NS * BATCH * CH];  // v partials
__device__ float g_op[NS * BATCH * CH];  // o partials
__device__ float g_o [BATCH * CH];       // final per-batch output vector

// ---------------------------------------------------------------------------
// KA: per (batch, split) block — recompute ctx+LN (cheap), then partial v.
// grid (BATCH, NS), 256 threads.
// ---------------------------------------------------------------------------
__global__ void __launch_bounds__(CH) ka_ln_vpart(
    const float* __restrict__ param,    // (B, 16)
    const float* __restrict__ Wparam,   // (16, 256)
    const float* __restrict__ bparam,   // (256)
    const float* __restrict__ gamma,    // (256)
    const float* __restrict__ beta,     // (256)
    const float* __restrict__ Wkv)      // (256, 512)
{
    const int b = blockIdx.x;
    const int s = blockIdx.y;
    const int c = threadIdx.x;

    __shared__ float sh_y[CH];
    __shared__ float red[8];

    // ctx[b][c]
    float ctx = bparam[c];
    #pragma unroll
    for (int p = 0; p < PDIM; p++)
        ctx = fmaf(param[b * PDIM + p], Wparam[p * CH + c], ctx);

    // mean
    float sum = ctx;
    #pragma unroll
    for (int off = 16; off > 0; off >>= 1)
        sum += __shfl_xor_sync(0xffffffffu, sum, off);
    if ((c & 31) == 0) red[c >> 5] = sum;
    __syncthreads();
    float mean = 0.f;
    #pragma unroll
    for (int i = 0; i < 8; i++) mean += red[i];
    mean *= (1.0f / CH);

    // variance
    float d = ctx - mean;
    float s2 = d * d;
    __syncthreads();
    #pragma unroll
    for (int off = 16; off > 0; off >>= 1)
        s2 += __shfl_xor_sync(0xffffffffu, s2, off);
    if ((c & 31) == 0) red[c >> 5] = s2;
    __syncthreads();
    float var = 0.f;
    #pragma unroll
    for (int i = 0; i < 8; i++) var += red[i];
    var *= (1.0f / CH);

    sh_y[c] = d * rsqrtf(var + EPSV) * gamma[c] + beta[c];
    __syncthreads();

    // partial v over j in [s*JSP, s*JSP+JSP)
    const int j0 = s * JSP;
    float acc = 0.f;
    #pragma unroll
    for (int jj = 0; jj < JSP; jj++)
        acc = fmaf(sh_y[j0 + jj], Wkv[(j0 + jj) * (2 * CH) + CH + c], acc);

    g_vp[(s * BATCH + b) * CH + c] = acc;
}

// ---------------------------------------------------------------------------
// KB: reduce v partials into shared, then partial o.
// grid (BATCH, NS), 256 threads.
// ---------------------------------------------------------------------------
__global__ void __launch_bounds__(CH) kb_opart(
    const float* __restrict__ Wout)     // (256, 256)
{
    const int b = blockIdx.x;
    const int s = blockIdx.y;
    const int c = threadIdx.x;

    __shared__ float sh_v[CH];

    float v = 0.f;
    #pragma unroll
    for (int ss = 0; ss < NS; ss++)
        v += g_vp[(ss * BATCH + b) * CH + c];
    sh_v[c] = v;
    __syncthreads();

    const int j0 = s * JSP;
    float acc = 0.f;
    #pragma unroll
    for (int jj = 0; jj < JSP; jj++)
        acc = fmaf(sh_v[j0 + jj], Wout[(j0 + jj) * CH + c], acc);

    g_op[(s * BATCH + b) * CH + c] = acc;
}

// ---------------------------------------------------------------------------
// KC: reduce o partials + bout → g_o. grid BATCH, 256 threads.
// ---------------------------------------------------------------------------
__global__ void __launch_bounds__(CH) kc_oreduce(
    const float* __restrict__ bout)
{
    const int b = blockIdx.x;
    const int c = threadIdx.x;

    float o = bout[c];
    #pragma unroll
    for (int ss = 0; ss < NS; ss++)
        o += g_op[(ss * BATCH + b) * CH + c];

    g_o[b * CH + c] = o;
}

// ---------------------------------------------------------------------------
// KD: out[b,n,c] = img[b,n,c] + o[b,c]. Grid-stride, 4 coalesced float4/thread.
// ---------------------------------------------------------------------------
#define KD_BLOCKS  512
#define KD_THREADS 256

__global__ void __launch_bounds__(KD_THREADS) kd_broadcast_add(
    const float* __restrict__ img,
    float* __restrict__ out)
{
    const int total4  = (BATCH * SEQ * CH) / 4;          // 524288
    const int nthread = KD_BLOCKS * KD_THREADS;          // 131072
    int i = blockIdx.x * KD_THREADS + threadIdx.x;

    #pragma unroll 4
    for (int k = 0; k < total4 / nthread; k++, i += nthread) {
        const int base = i << 2;
        const int c = base & (CH - 1);
        const int b = base >> 18;                        // 1024*256 = 2^18

        float4 x  = reinterpret_cast<const float4*>(img)[i];
        float4 ov = *reinterpret_cast<const float4*>(&g_o[b * CH + c]);
        x.x += ov.x; x.y += ov.y; x.z += ov.z; x.w += ov.w;
        reinterpret_cast<float4*>(out)[i] = x;
    }
}

// ---------------------------------------------------------------------------
// Launch. Input order: img_tokens, param_tokens, img_norm_g, img_norm_b, Wq,
// Wparam, bparam, ctx_norm_g, ctx_norm_b, Wkv, Wout, bout
// (q/attention are algebraically dead: softmax of a constant row is 1/N, and
//  sum_m (1/N) * v = v exactly, so out = img + (LN(ctx) @ Wv) @ Wout + bout.)
// ---------------------------------------------------------------------------
extern "C" void kernel_launch(void* const* d_in, const int* in_sizes, int n_in,
                              void* d_out, int out_size)
{
    const float* img    = (const float*)d_in[0];
    const float* param  = (const float*)d_in[1];
    const float* Wparam = (const float*)d_in[5];
    const float* bparam = (const float*)d_in[6];
    const float* ctx_g  = (const float*)d_in[7];
    const float* ctx_b  = (const float*)d_in[8];
    const float* Wkv    = (const float*)d_in[9];
    const float* Wout   = (const float*)d_in[10];
    const float* bout   = (const float*)d_in[11];
    float* out = (float*)d_out;

    dim3 gsplit(BATCH, NS);
    ka_ln_vpart<<<gsplit, CH>>>(param, Wparam, bparam, ctx_g, ctx_b, Wkv);
    kb_opart   <<<gsplit, CH>>>(Wout);
    kc_oreduce <<<BATCH, CH>>>(bout);
    kd_broadcast_add<<<KD_BLOCKS, KD_THREADS>>>(img, out);
}